// round 8
// baseline (speedup 1.0000x reference)
#include <cuda_runtime.h>
#include <math.h>
#include <stdint.h>

#define D_MODEL 1024
#define NUM_HEADS 16
#define DK 64
#define BATCH 2
#define SEQ 2048
#define M_TOTAL (BATCH * SEQ)   // 4096

// ---------------- scratch (no cudaMalloc allowed) ----------------
__device__ float g_Q[(size_t)M_TOTAL * D_MODEL];
__device__ float g_K[(size_t)M_TOTAL * D_MODEL];
__device__ float g_V[(size_t)M_TOTAL * D_MODEL];
__device__ float g_A[(size_t)M_TOTAL * D_MODEL];

// ================= helpers =================
__device__ __forceinline__ uint32_t f2tf32(float f) {
    uint32_t r;
    asm("cvt.rna.tf32.f32 %0, %1;" : "=r"(r) : "f"(f));
    return r;
}

__device__ __forceinline__ void mma_tf32(float c[4],
                                         uint32_t a0, uint32_t a1, uint32_t a2, uint32_t a3,
                                         uint32_t b0, uint32_t b1) {
    asm volatile(
        "mma.sync.aligned.m16n8k8.row.col.f32.tf32.tf32.f32 "
        "{%0,%1,%2,%3}, {%4,%5,%6,%7}, {%8,%9}, {%0,%1,%2,%3};"
        : "+f"(c[0]), "+f"(c[1]), "+f"(c[2]), "+f"(c[3])
        : "r"(a0), "r"(a1), "r"(a2), "r"(a3), "r"(b0), "r"(b1));
}

// =================================================================
// mma.sync tf32 NT GEMM (R6-proven): CTA 128x256, BK=32, 512 thr.
// =================================================================
#define TM 128
#define TN 256
#define BK 32
#define NC (D_MODEL / BK)
#define SSTR 36
#define A_BUF_FLOATS (TM * SSTR)
#define B_BUF_FLOATS (TN * SSTR)
#define SMEM_GEMM ((2 * A_BUF_FLOATS + 2 * B_BUF_FLOATS) * 4)

__device__ __forceinline__ void gemm_body(const float* __restrict__ A,
                                          const float* __restrict__ B,
                                          float* __restrict__ C)
{
    extern __shared__ float sm[];
    float* Asm[2] = { sm, sm + A_BUF_FLOATS };
    float* Bsm[2] = { sm + 2 * A_BUF_FLOATS, sm + 2 * A_BUF_FLOATS + B_BUF_FLOATS };

    const int tid = threadIdx.x;
    const int wid = tid >> 5;
    const int lane = tid & 31;
    const int g = lane >> 2;
    const int t = lane & 3;
    const int warp_m = wid >> 3;
    const int warp_n = wid & 7;
    const int bm = blockIdx.y * TM;
    const int bn = blockIdx.x * TN;

    const int rA[2] = { (tid) >> 3, (tid + 512) >> 3 };
    const int cA = (tid & 7) * 4;
    int rB[4], cB = (tid & 7) * 4;
#pragma unroll
    for (int j = 0; j < 4; j++) rB[j] = (tid + j * 512) >> 3;

    float c[4][4][4];
#pragma unroll
    for (int mt = 0; mt < 4; mt++)
#pragma unroll
        for (int nt = 0; nt < 4; nt++)
#pragma unroll
            for (int i = 0; i < 4; i++) c[mt][nt][i] = 0.f;

    {
        float4 ra[2], rb[4];
#pragma unroll
        for (int j = 0; j < 2; j++)
            ra[j] = *(const float4*)(A + (size_t)(bm + rA[j]) * D_MODEL + cA);
#pragma unroll
        for (int j = 0; j < 4; j++)
            rb[j] = *(const float4*)(B + (size_t)(bn + rB[j]) * D_MODEL + cB);
#pragma unroll
        for (int j = 0; j < 2; j++) {
            uint4 u = { f2tf32(ra[j].x), f2tf32(ra[j].y), f2tf32(ra[j].z), f2tf32(ra[j].w) };
            *(uint4*)&Asm[0][rA[j] * SSTR + cA] = u;
        }
#pragma unroll
        for (int j = 0; j < 4; j++) {
            uint4 u = { f2tf32(rb[j].x), f2tf32(rb[j].y), f2tf32(rb[j].z), f2tf32(rb[j].w) };
            *(uint4*)&Bsm[0][rB[j] * SSTR + cB] = u;
        }
    }
    __syncthreads();

    for (int kc = 0; kc < NC; kc++) {
        const int cur = kc & 1;
        const bool more = (kc + 1 < NC);
        float4 ra[2], rb[4];
        if (more) {
            const int k1 = (kc + 1) * BK;
#pragma unroll
            for (int j = 0; j < 2; j++)
                ra[j] = *(const float4*)(A + (size_t)(bm + rA[j]) * D_MODEL + k1 + cA);
#pragma unroll
            for (int j = 0; j < 4; j++)
                rb[j] = *(const float4*)(B + (size_t)(bn + rB[j]) * D_MODEL + k1 + cB);
        }

        const uint32_t* As = (const uint32_t*)Asm[cur];
        const uint32_t* Bs = (const uint32_t*)Bsm[cur];
#pragma unroll
        for (int ks = 0; ks < 4; ks++) {
            const int k0 = ks * 8;
            uint32_t af[4][4];
#pragma unroll
            for (int mt = 0; mt < 4; mt++) {
                const int rb_ = warp_m * 64 + mt * 16;
                af[mt][0] = As[(rb_ + g) * SSTR + k0 + t];
                af[mt][1] = As[(rb_ + g + 8) * SSTR + k0 + t];
                af[mt][2] = As[(rb_ + g) * SSTR + k0 + t + 4];
                af[mt][3] = As[(rb_ + g + 8) * SSTR + k0 + t + 4];
            }
            uint32_t bf[4][2];
#pragma unroll
            for (int nt = 0; nt < 4; nt++) {
                const int nb = warp_n * 32 + nt * 8;
                bf[nt][0] = Bs[(nb + g) * SSTR + k0 + t];
                bf[nt][1] = Bs[(nb + g) * SSTR + k0 + t + 4];
            }
#pragma unroll
            for (int mt = 0; mt < 4; mt++)
#pragma unroll
                for (int nt = 0; nt < 4; nt++)
                    mma_tf32(c[mt][nt], af[mt][0], af[mt][1], af[mt][2], af[mt][3],
                             bf[nt][0], bf[nt][1]);
        }

        if (more) {
            const int nxt = cur ^ 1;
#pragma unroll
            for (int j = 0; j < 2; j++) {
                uint4 u = { f2tf32(ra[j].x), f2tf32(ra[j].y), f2tf32(ra[j].z), f2tf32(ra[j].w) };
                *(uint4*)&Asm[nxt][rA[j] * SSTR + cA] = u;
            }
#pragma unroll
            for (int j = 0; j < 4; j++) {
                uint4 u = { f2tf32(rb[j].x), f2tf32(rb[j].y), f2tf32(rb[j].z), f2tf32(rb[j].w) };
                *(uint4*)&Bsm[nxt][rB[j] * SSTR + cB] = u;
            }
        }
        __syncthreads();
    }

#pragma unroll
    for (int mt = 0; mt < 4; mt++) {
        const int row0 = bm + warp_m * 64 + mt * 16 + g;
#pragma unroll
        for (int nt = 0; nt < 4; nt++) {
            const int col = bn + warp_n * 32 + nt * 8 + 2 * t;
            *(float2*)(C + (size_t)row0 * D_MODEL + col) =
                make_float2(c[mt][nt][0], c[mt][nt][1]);
            *(float2*)(C + (size_t)(row0 + 8) * D_MODEL + col) =
                make_float2(c[mt][nt][2], c[mt][nt][3]);
        }
    }
}

__global__ __launch_bounds__(512, 1)
void gemm_qkv(const float* __restrict__ x,
              const float* __restrict__ Wq, const float* __restrict__ Wk,
              const float* __restrict__ Wv,
              float* __restrict__ Cq, float* __restrict__ Ck,
              float* __restrict__ Cv)
{
    const float* B = (blockIdx.z == 0) ? Wq : (blockIdx.z == 1) ? Wk : Wv;
    float*       C = (blockIdx.z == 0) ? Cq : (blockIdx.z == 1) ? Ck : Cv;
    gemm_body(x, B, C);
}

__global__ __launch_bounds__(512, 1)
void gemm_mma(const float* __restrict__ A, const float* __restrict__ B,
              float* __restrict__ C)
{
    gemm_body(A, B, C);
}

// =================================================================
// Flash attention, mma.sync tf32. R6 winner + double-buffered K/V
// (ONE __syncthreads per KV tile instead of two).
// CTA: 128 queries x one (b,h). 8 warps; warp owns 16 query rows.
// =================================================================
#define BQ 128
#define BKV 64
#define NTILE (SEQ / BKV)
#define FSTR 68
#define VSTR 69
#define KBUF (64 * FSTR)                    // 4352 words
#define VBUF (64 * VSTR)                    // 4416 words
#define SM_K0 0
#define SM_K1 KBUF
#define SM_V0 (2 * KBUF)
#define SM_V1 (2 * KBUF + VBUF)
#define SM_PS (2 * KBUF + 2 * VBUF)         // 17536
#define SM_BIAS (SM_PS + 8 * 16 * FSTR)     // 26240
#define SMEM_ATTN ((SM_BIAS + 128) * 4)     // 105472 B

__global__ __launch_bounds__(256, 1)
void flash_mma(const int* __restrict__ mask)
{
    extern __shared__ float sf[];
    uint32_t* Kbuf[2] = { (uint32_t*)(sf + SM_K0), (uint32_t*)(sf + SM_K1) };
    uint32_t* Vbuf[2] = { (uint32_t*)(sf + SM_V0), (uint32_t*)(sf + SM_V1) };
    float*    bbuf[2] = { sf + SM_BIAS, sf + SM_BIAS + 64 };

    const int tid = threadIdx.x;
    const int w = tid >> 5, lane = tid & 31;
    const int g = lane >> 2, t = lane & 3;
    const int qt = blockIdx.x, bh = blockIdx.y;
    const int b = bh >> 4, h = bh & 15;
    const int q0 = qt * BQ;
    const int m0 = w * 16;

    const float* Qg = g_Q + (size_t)(b * SEQ + q0) * D_MODEL + h * DK;
    const float* Kg = g_K + (size_t)(b * SEQ) * D_MODEL + h * DK;
    const float* Vg = g_V + (size_t)(b * SEQ) * D_MODEL + h * DK;
    const int* mrow = mask + b * SEQ;

    uint32_t* Pw = (uint32_t*)(sf + SM_PS) + w * 16 * FSTR;

    // ---- stage Q (scaled) into warp-private buffer, read A-fragments ----
#pragma unroll
    for (int it = 0; it < 8; it++) {
        int idx = lane + it * 32;        // 0..255
        int row = idx >> 4;              // 0..15
        int c4  = idx & 15;
        float4 v = *(const float4*)(Qg + (size_t)(m0 + row) * D_MODEL + c4 * 4);
        uint4 u = { f2tf32(v.x * 0.125f), f2tf32(v.y * 0.125f),
                    f2tf32(v.z * 0.125f), f2tf32(v.w * 0.125f) };
        *(uint4*)(Pw + row * FSTR + c4 * 4) = u;
    }
    __syncwarp();
    uint32_t qf[8][4];
#pragma unroll
    for (int k8 = 0; k8 < 8; k8++) {
        qf[k8][0] = Pw[g * FSTR + k8 * 8 + t];
        qf[k8][1] = Pw[(g + 8) * FSTR + k8 * 8 + t];
        qf[k8][2] = Pw[g * FSTR + k8 * 8 + t + 4];
        qf[k8][3] = Pw[(g + 8) * FSTR + k8 * 8 + t + 4];
    }

    float mr0 = -INFINITY, mr1 = -INFINITY, l0 = 0.f, l1 = 0.f;
    float of[8][4];
#pragma unroll
    for (int nt = 0; nt < 8; nt++)
#pragma unroll
        for (int i = 0; i < 4; i++) of[nt][i] = 0.f;

    int rows[4], c4s[4];
#pragma unroll
    for (int it = 0; it < 4; it++) {
        int idx = tid + it * 256;
        rows[it] = idx >> 4;
        c4s[it]  = idx & 15;
    }

    // ---- prologue: load tile 0, commit to buffer 0 ----
    {
        float4 kreg[4], vreg[4];
#pragma unroll
        for (int it = 0; it < 4; it++) {
            kreg[it] = *(const float4*)(Kg + (size_t)rows[it] * D_MODEL + c4s[it] * 4);
            vreg[it] = *(const float4*)(Vg + (size_t)rows[it] * D_MODEL + c4s[it] * 4);
        }
        int m0v = (tid < 64) ? mrow[tid] : 1;
#pragma unroll
        for (int it = 0; it < 4; it++) {
            const int row = rows[it], c4 = c4s[it];
            uint4 u = { f2tf32(kreg[it].x), f2tf32(kreg[it].y),
                        f2tf32(kreg[it].z), f2tf32(kreg[it].w) };
            *(uint4*)(Kbuf[0] + row * FSTR + c4 * 4) = u;
            Vbuf[0][(c4 * 4 + 0) * VSTR + row] = f2tf32(vreg[it].x);
            Vbuf[0][(c4 * 4 + 1) * VSTR + row] = f2tf32(vreg[it].y);
            Vbuf[0][(c4 * 4 + 2) * VSTR + row] = f2tf32(vreg[it].z);
            Vbuf[0][(c4 * 4 + 3) * VSTR + row] = f2tf32(vreg[it].w);
        }
        if (tid < 64) bbuf[0][tid] = m0v ? 0.f : -1e30f;
    }
    __syncthreads();

    for (int kt = 0; kt < NTILE; kt++) {
        const int cur = kt & 1;
        const bool more = (kt + 1 < NTILE);
        const uint32_t* Ku = Kbuf[cur];
        const uint32_t* Vu = Vbuf[cur];
        const float* bias = bbuf[cur];

        // ---- prefetch next tile into registers ----
        float4 kreg[4], vreg[4];
        int mreg = 1;
        if (more) {
            const int k1 = (kt + 1) * BKV;
#pragma unroll
            for (int it = 0; it < 4; it++) {
                kreg[it] = *(const float4*)(Kg + (size_t)(k1 + rows[it]) * D_MODEL + c4s[it] * 4);
                vreg[it] = *(const float4*)(Vg + (size_t)(k1 + rows[it]) * D_MODEL + c4s[it] * 4);
            }
            if (tid < 64) mreg = mrow[k1 + tid];
        }

        // ---- S = Q K^T ----
        float s[8][4];
#pragma unroll
        for (int nt = 0; nt < 8; nt++)
#pragma unroll
            for (int i = 0; i < 4; i++) s[nt][i] = 0.f;
#pragma unroll
        for (int k8 = 0; k8 < 8; k8++) {
#pragma unroll
            for (int nt = 0; nt < 8; nt++) {
                uint32_t b0 = Ku[(nt * 8 + g) * FSTR + k8 * 8 + t];
                uint32_t b1 = Ku[(nt * 8 + g) * FSTR + k8 * 8 + t + 4];
                mma_tf32(s[nt], qf[k8][0], qf[k8][1], qf[k8][2], qf[k8][3], b0, b1);
            }
        }

        // ---- online softmax in registers ----
        float tm0 = -INFINITY, tm1 = -INFINITY;
#pragma unroll
        for (int nt = 0; nt < 8; nt++) {
            float b0 = bias[nt * 8 + 2 * t];
            float b1 = bias[nt * 8 + 2 * t + 1];
            s[nt][0] += b0; s[nt][1] += b1;
            s[nt][2] += b0; s[nt][3] += b1;
            tm0 = fmaxf(tm0, fmaxf(s[nt][0], s[nt][1]));
            tm1 = fmaxf(tm1, fmaxf(s[nt][2], s[nt][3]));
        }
        tm0 = fmaxf(tm0, __shfl_xor_sync(0xffffffffu, tm0, 1));
        tm0 = fmaxf(tm0, __shfl_xor_sync(0xffffffffu, tm0, 2));
        tm1 = fmaxf(tm1, __shfl_xor_sync(0xffffffffu, tm1, 1));
        tm1 = fmaxf(tm1, __shfl_xor_sync(0xffffffffu, tm1, 2));

        float mn0 = fmaxf(mr0, tm0), mn1 = fmaxf(mr1, tm1);
        float a0 = __expf(mr0 - mn0), a1 = __expf(mr1 - mn1);
        float ls0 = 0.f, ls1 = 0.f;
#pragma unroll
        for (int nt = 0; nt < 8; nt++) {
            float p0 = __expf(s[nt][0] - mn0);
            float p1 = __expf(s[nt][1] - mn0);
            float p2 = __expf(s[nt][2] - mn1);
            float p3 = __expf(s[nt][3] - mn1);
            ls0 += p0 + p1; ls1 += p2 + p3;
            uint2 u01 = { f2tf32(p0), f2tf32(p1) };
            uint2 u23 = { f2tf32(p2), f2tf32(p3) };
            *(uint2*)(Pw + g * FSTR + nt * 8 + 2 * t) = u01;
            *(uint2*)(Pw + (g + 8) * FSTR + nt * 8 + 2 * t) = u23;
        }
        ls0 += __shfl_xor_sync(0xffffffffu, ls0, 1);
        ls0 += __shfl_xor_sync(0xffffffffu, ls0, 2);
        ls1 += __shfl_xor_sync(0xffffffffu, ls1, 1);
        ls1 += __shfl_xor_sync(0xffffffffu, ls1, 2);

        mr0 = mn0; mr1 = mn1;
        l0 = l0 * a0 + ls0;
        l1 = l1 * a1 + ls1;
#pragma unroll
        for (int nt = 0; nt < 8; nt++) {
            of[nt][0] *= a0; of[nt][1] *= a0;
            of[nt][2] *= a1; of[nt][3] *= a1;
        }
        __syncwarp();

        // ---- O += P V ----
#pragma unroll
        for (int k8 = 0; k8 < 8; k8++) {
            uint32_t pa0 = Pw[g * FSTR + k8 * 8 + t];
            uint32_t pa1 = Pw[(g + 8) * FSTR + k8 * 8 + t];
            uint32_t pa2 = Pw[g * FSTR + k8 * 8 + t + 4];
            uint32_t pa3 = Pw[(g + 8) * FSTR + k8 * 8 + t + 4];
#pragma unroll
            for (int nt = 0; nt < 8; nt++) {
                uint32_t b0 = Vu[(nt * 8 + g) * VSTR + k8 * 8 + t];
                uint32_t b1 = Vu[(nt * 8 + g) * VSTR + k8 * 8 + t + 4];
                mma_tf32(of[nt], pa0, pa1, pa2, pa3, b0, b1);
            }
        }

        // ---- commit prefetched tile to alternate buffer, single barrier ----
        if (more) {
            const int nxt = cur ^ 1;
#pragma unroll
            for (int it = 0; it < 4; it++) {
                const int row = rows[it], c4 = c4s[it];
                uint4 u = { f2tf32(kreg[it].x), f2tf32(kreg[it].y),
                            f2tf32(kreg[it].z), f2tf32(kreg[it].w) };
                *(uint4*)(Kbuf[nxt] + row * FSTR + c4 * 4) = u;
                Vbuf[nxt][(c4 * 4 + 0) * VSTR + row] = f2tf32(vreg[it].x);
                Vbuf[nxt][(c4 * 4 + 1) * VSTR + row] = f2tf32(vreg[it].y);
                Vbuf[nxt][(c4 * 4 + 2) * VSTR + row] = f2tf32(vreg[it].z);
                Vbuf[nxt][(c4 * 4 + 3) * VSTR + row] = f2tf32(vreg[it].w);
            }
            if (tid < 64) bbuf[nxt][tid] = mreg ? 0.f : -1e30f;
            __syncthreads();
        }
    }

    // ---- epilogue ----
    const float li0 = 1.f / l0, li1 = 1.f / l1;
    float* Og = g_A + (size_t)(b * SEQ + q0 + m0) * D_MODEL + h * DK;
#pragma unroll
    for (int nt = 0; nt < 8; nt++) {
        const int col = nt * 8 + 2 * t;
        *(float2*)(Og + (size_t)g * D_MODEL + col) =
            make_float2(of[nt][0] * li0, of[nt][1] * li0);
        *(float2*)(Og + (size_t)(g + 8) * D_MODEL + col) =
            make_float2(of[nt][2] * li1, of[nt][3] * li1);
    }
}

// =================================================================
// launch
// =================================================================
extern "C" void kernel_launch(void* const* d_in, const int* in_sizes, int n_in,
                              void* d_out, int out_size)
{
    const float* x    = (const float*)d_in[0];
    const int*   mask = (const int*)d_in[1];
    const float* Wq   = (const float*)d_in[2];
    const float* Wk   = (const float*)d_in[3];
    const float* Wv   = (const float*)d_in[4];
    const float* Wo   = (const float*)d_in[5];
    float* out = (float*)d_out;

    float *gq, *gk, *gv, *ga;
    cudaGetSymbolAddress((void**)&gq, g_Q);
    cudaGetSymbolAddress((void**)&gk, g_K);
    cudaGetSymbolAddress((void**)&gv, g_V);
    cudaGetSymbolAddress((void**)&ga, g_A);

    cudaFuncSetAttribute(gemm_qkv,
                         cudaFuncAttributeMaxDynamicSharedMemorySize, SMEM_GEMM);
    cudaFuncSetAttribute(gemm_mma,
                         cudaFuncAttributeMaxDynamicSharedMemorySize, SMEM_GEMM);
    cudaFuncSetAttribute(flash_mma,
                         cudaFuncAttributeMaxDynamicSharedMemorySize, SMEM_ATTN);

    dim3 qkv_grid(D_MODEL / TN, M_TOTAL / TM, 3);  // (4, 32, 3) = 384 CTAs
    gemm_qkv<<<qkv_grid, 512, SMEM_GEMM>>>(x, Wq, Wk, Wv, gq, gk, gv);

    dim3 attn_grid(SEQ / BQ, BATCH * NUM_HEADS);   // (16, 32) = 512 CTAs
    flash_mma<<<attn_grid, 256, SMEM_ATTN>>>(mask);

    dim3 ggrid(D_MODEL / TN, M_TOTAL / TM);        // (4, 32)
    gemm_mma<<<ggrid, 512, SMEM_GEMM>>>(ga, Wo, out);
}

// round 9
// speedup vs baseline: 1.2124x; 1.2124x over previous
#include <cuda_runtime.h>
#include <math.h>
#include <stdint.h>

#define D_MODEL 1024
#define NUM_HEADS 16
#define DK 64
#define BATCH 2
#define SEQ 2048
#define M_TOTAL (BATCH * SEQ)   // 4096

// ---------------- scratch (no cudaMalloc allowed) ----------------
__device__ float g_Q[(size_t)M_TOTAL * D_MODEL];
__device__ float g_K[(size_t)M_TOTAL * D_MODEL];
__device__ float g_V[(size_t)M_TOTAL * D_MODEL];
__device__ float g_A[(size_t)M_TOTAL * D_MODEL];

// ================= helpers =================
__device__ __forceinline__ uint32_t f2tf32(float f) {
    uint32_t r;
    asm("cvt.rna.tf32.f32 %0, %1;" : "=r"(r) : "f"(f));
    return r;
}

__device__ __forceinline__ void mma_tf32(float c[4],
                                         uint32_t a0, uint32_t a1, uint32_t a2, uint32_t a3,
                                         uint32_t b0, uint32_t b1) {
    asm volatile(
        "mma.sync.aligned.m16n8k8.row.col.f32.tf32.tf32.f32 "
        "{%0,%1,%2,%3}, {%4,%5,%6,%7}, {%8,%9}, {%0,%1,%2,%3};"
        : "+f"(c[0]), "+f"(c[1]), "+f"(c[2]), "+f"(c[3])
        : "r"(a0), "r"(a1), "r"(a2), "r"(a3), "r"(b0), "r"(b1));
}

// =================================================================
// mma.sync tf32 NT GEMM: C[M,1024] = A[M,1024] * B[1024,1024]^T
// CTA tile 128x256, BK=32, 256 threads (8 warps, 2x4).
// Warp tile 64x64: 4 m-tiles x 8 n-tiles -> 1.0 MMA per LDS word.
// =================================================================
#define TM 128
#define TN 256
#define BK 32
#define NC (D_MODEL / BK)
#define SSTR 36
#define A_BUF_FLOATS (TM * SSTR)
#define B_BUF_FLOATS (TN * SSTR)
#define SMEM_GEMM ((2 * A_BUF_FLOATS + 2 * B_BUF_FLOATS) * 4)

__device__ __forceinline__ void gemm_body(const float* __restrict__ A,
                                          const float* __restrict__ B,
                                          float* __restrict__ C)
{
    extern __shared__ float sm[];
    float* Asm[2] = { sm, sm + A_BUF_FLOATS };
    float* Bsm[2] = { sm + 2 * A_BUF_FLOATS, sm + 2 * A_BUF_FLOATS + B_BUF_FLOATS };

    const int tid = threadIdx.x;
    const int wid = tid >> 5;
    const int lane = tid & 31;
    const int g = lane >> 2;
    const int t = lane & 3;
    const int warp_m = wid >> 2;   // 0..1
    const int warp_n = wid & 3;    // 0..3
    const int bm = blockIdx.y * TM;
    const int bn = blockIdx.x * TN;

    // staging coords: A 128x32 -> 4 float4/thread; B 256x32 -> 8 float4/thread
    int rA[4], rB[8];
    const int cc = (tid & 7) * 4;
#pragma unroll
    for (int j = 0; j < 4; j++) rA[j] = (tid + j * 256) >> 3;   // 0..127
#pragma unroll
    for (int j = 0; j < 8; j++) rB[j] = (tid + j * 256) >> 3;   // 0..255

    float c[4][8][4];
#pragma unroll
    for (int mt = 0; mt < 4; mt++)
#pragma unroll
        for (int nt = 0; nt < 8; nt++)
#pragma unroll
            for (int i = 0; i < 4; i++) c[mt][nt][i] = 0.f;

    // prologue: stage chunk 0
    {
#pragma unroll
        for (int j = 0; j < 4; j++) {
            float4 v = *(const float4*)(A + (size_t)(bm + rA[j]) * D_MODEL + cc);
            uint4 u = { f2tf32(v.x), f2tf32(v.y), f2tf32(v.z), f2tf32(v.w) };
            *(uint4*)&Asm[0][rA[j] * SSTR + cc] = u;
        }
#pragma unroll
        for (int j = 0; j < 8; j++) {
            float4 v = *(const float4*)(B + (size_t)(bn + rB[j]) * D_MODEL + cc);
            uint4 u = { f2tf32(v.x), f2tf32(v.y), f2tf32(v.z), f2tf32(v.w) };
            *(uint4*)&Bsm[0][rB[j] * SSTR + cc] = u;
        }
    }
    __syncthreads();

    for (int kc = 0; kc < NC; kc++) {
        const int cur = kc & 1;
        const bool more = (kc + 1 < NC);
        float4 ra[4], rb[8];
        if (more) {
            const int k1 = (kc + 1) * BK;
#pragma unroll
            for (int j = 0; j < 4; j++)
                ra[j] = *(const float4*)(A + (size_t)(bm + rA[j]) * D_MODEL + k1 + cc);
#pragma unroll
            for (int j = 0; j < 8; j++)
                rb[j] = *(const float4*)(B + (size_t)(bn + rB[j]) * D_MODEL + k1 + cc);
        }

        const uint32_t* As = (const uint32_t*)Asm[cur];
        const uint32_t* Bs = (const uint32_t*)Bsm[cur];
#pragma unroll
        for (int ks = 0; ks < 4; ks++) {
            const int k0 = ks * 8;
            uint32_t af[4][4];
#pragma unroll
            for (int mt = 0; mt < 4; mt++) {
                const int rb_ = warp_m * 64 + mt * 16;
                af[mt][0] = As[(rb_ + g) * SSTR + k0 + t];
                af[mt][1] = As[(rb_ + g + 8) * SSTR + k0 + t];
                af[mt][2] = As[(rb_ + g) * SSTR + k0 + t + 4];
                af[mt][3] = As[(rb_ + g + 8) * SSTR + k0 + t + 4];
            }
            uint32_t bf[8][2];
#pragma unroll
            for (int nt = 0; nt < 8; nt++) {
                const int nb = warp_n * 64 + nt * 8;
                bf[nt][0] = Bs[(nb + g) * SSTR + k0 + t];
                bf[nt][1] = Bs[(nb + g) * SSTR + k0 + t + 4];
            }
#pragma unroll
            for (int mt = 0; mt < 4; mt++)
#pragma unroll
                for (int nt = 0; nt < 8; nt++)
                    mma_tf32(c[mt][nt], af[mt][0], af[mt][1], af[mt][2], af[mt][3],
                             bf[nt][0], bf[nt][1]);
        }

        if (more) {
            const int nxt = cur ^ 1;
#pragma unroll
            for (int j = 0; j < 4; j++) {
                uint4 u = { f2tf32(ra[j].x), f2tf32(ra[j].y), f2tf32(ra[j].z), f2tf32(ra[j].w) };
                *(uint4*)&Asm[nxt][rA[j] * SSTR + cc] = u;
            }
#pragma unroll
            for (int j = 0; j < 8; j++) {
                uint4 u = { f2tf32(rb[j].x), f2tf32(rb[j].y), f2tf32(rb[j].z), f2tf32(rb[j].w) };
                *(uint4*)&Bsm[nxt][rB[j] * SSTR + cc] = u;
            }
        }
        __syncthreads();
    }

#pragma unroll
    for (int mt = 0; mt < 4; mt++) {
        const int row0 = bm + warp_m * 64 + mt * 16 + g;
#pragma unroll
        for (int nt = 0; nt < 8; nt++) {
            const int col = bn + warp_n * 64 + nt * 8 + 2 * t;
            *(float2*)(C + (size_t)row0 * D_MODEL + col) =
                make_float2(c[mt][nt][0], c[mt][nt][1]);
            *(float2*)(C + (size_t)(row0 + 8) * D_MODEL + col) =
                make_float2(c[mt][nt][2], c[mt][nt][3]);
        }
    }
}

__global__ __launch_bounds__(256, 1)
void gemm_qkv(const float* __restrict__ x,
              const float* __restrict__ Wq, const float* __restrict__ Wk,
              const float* __restrict__ Wv,
              float* __restrict__ Cq, float* __restrict__ Ck,
              float* __restrict__ Cv)
{
    const float* B = (blockIdx.z == 0) ? Wq : (blockIdx.z == 1) ? Wk : Wv;
    float*       C = (blockIdx.z == 0) ? Cq : (blockIdx.z == 1) ? Ck : Cv;
    gemm_body(x, B, C);
}

__global__ __launch_bounds__(256, 1)
void gemm_mma(const float* __restrict__ A, const float* __restrict__ B,
              float* __restrict__ C)
{
    gemm_body(A, B, C);
}

// =================================================================
// Flash attention, mma.sync tf32 (exact R6 winner — 418us proven).
// CTA: 128 queries x one (b,h). 8 warps; warp owns 16 query rows.
// KV tile 64, register prefetch of next tile, V stride 69.
// =================================================================
#define BQ 128
#define BKV 64
#define NTILE (SEQ / BKV)
#define FSTR 68
#define VSTR 69
#define SM_KS 0
#define SM_VT (64 * FSTR)                  // 4352
#define SM_PS (SM_VT + 64 * VSTR)          // 8768
#define SM_BIAS (SM_PS + 8 * 16 * FSTR)    // 17472
#define SMEM_ATTN ((SM_BIAS + 64) * 4)     // 70144 B

__global__ __launch_bounds__(256, 1)
void flash_mma(const int* __restrict__ mask)
{
    extern __shared__ float sf[];
    uint32_t* Ku   = (uint32_t*)(sf + SM_KS);
    uint32_t* Vu   = (uint32_t*)(sf + SM_VT);
    float*    bias = sf + SM_BIAS;

    const int tid = threadIdx.x;
    const int w = tid >> 5, lane = tid & 31;
    const int g = lane >> 2, t = lane & 3;
    const int qt = blockIdx.x, bh = blockIdx.y;
    const int b = bh >> 4, h = bh & 15;
    const int q0 = qt * BQ;
    const int m0 = w * 16;

    const float* Qg = g_Q + (size_t)(b * SEQ + q0) * D_MODEL + h * DK;
    const float* Kg = g_K + (size_t)(b * SEQ) * D_MODEL + h * DK;
    const float* Vg = g_V + (size_t)(b * SEQ) * D_MODEL + h * DK;
    const int* mrow = mask + b * SEQ;

    uint32_t* Pw = (uint32_t*)(sf + SM_PS) + w * 16 * FSTR;

    // ---- stage Q (scaled) into warp-private buffer, read A-fragments ----
#pragma unroll
    for (int it = 0; it < 8; it++) {
        int idx = lane + it * 32;        // 0..255
        int row = idx >> 4;              // 0..15
        int c4  = idx & 15;
        float4 v = *(const float4*)(Qg + (size_t)(m0 + row) * D_MODEL + c4 * 4);
        uint4 u = { f2tf32(v.x * 0.125f), f2tf32(v.y * 0.125f),
                    f2tf32(v.z * 0.125f), f2tf32(v.w * 0.125f) };
        *(uint4*)(Pw + row * FSTR + c4 * 4) = u;
    }
    __syncwarp();
    uint32_t qf[8][4];
#pragma unroll
    for (int k8 = 0; k8 < 8; k8++) {
        qf[k8][0] = Pw[g * FSTR + k8 * 8 + t];
        qf[k8][1] = Pw[(g + 8) * FSTR + k8 * 8 + t];
        qf[k8][2] = Pw[g * FSTR + k8 * 8 + t + 4];
        qf[k8][3] = Pw[(g + 8) * FSTR + k8 * 8 + t + 4];
    }

    float mr0 = -INFINITY, mr1 = -INFINITY, l0 = 0.f, l1 = 0.f;
    float of[8][4];
#pragma unroll
    for (int nt = 0; nt < 8; nt++)
#pragma unroll
        for (int i = 0; i < 4; i++) of[nt][i] = 0.f;

    int rows[4], c4s[4];
#pragma unroll
    for (int it = 0; it < 4; it++) {
        int idx = tid + it * 256;
        rows[it] = idx >> 4;
        c4s[it]  = idx & 15;
    }

    // ---- prefetch tile 0 into registers ----
    float4 kreg[4], vreg[4];
    int mreg = 1;
#pragma unroll
    for (int it = 0; it < 4; it++) {
        kreg[it] = *(const float4*)(Kg + (size_t)rows[it] * D_MODEL + c4s[it] * 4);
        vreg[it] = *(const float4*)(Vg + (size_t)rows[it] * D_MODEL + c4s[it] * 4);
    }
    if (tid < 64) mreg = mrow[tid];

    for (int kt = 0; kt < NTILE; kt++) {
        // ---- STS phase: commit prefetched tile to smem ----
#pragma unroll
        for (int it = 0; it < 4; it++) {
            const int row = rows[it], c4 = c4s[it];
            uint4 u = { f2tf32(kreg[it].x), f2tf32(kreg[it].y),
                        f2tf32(kreg[it].z), f2tf32(kreg[it].w) };
            *(uint4*)(Ku + row * FSTR + c4 * 4) = u;
            Vu[(c4 * 4 + 0) * VSTR + row] = f2tf32(vreg[it].x);
            Vu[(c4 * 4 + 1) * VSTR + row] = f2tf32(vreg[it].y);
            Vu[(c4 * 4 + 2) * VSTR + row] = f2tf32(vreg[it].z);
            Vu[(c4 * 4 + 3) * VSTR + row] = f2tf32(vreg[it].w);
        }
        if (tid < 64) bias[tid] = mreg ? 0.f : -1e30f;
        __syncthreads();

        // ---- prefetch next tile (latency hidden behind MMA phase) ----
        if (kt + 1 < NTILE) {
            const int k1 = (kt + 1) * BKV;
#pragma unroll
            for (int it = 0; it < 4; it++) {
                kreg[it] = *(const float4*)(Kg + (size_t)(k1 + rows[it]) * D_MODEL + c4s[it] * 4);
                vreg[it] = *(const float4*)(Vg + (size_t)(k1 + rows[it]) * D_MODEL + c4s[it] * 4);
            }
            if (tid < 64) mreg = mrow[k1 + tid];
        }

        // ---- S = Q K^T ----
        float s[8][4];
#pragma unroll
        for (int nt = 0; nt < 8; nt++)
#pragma unroll
            for (int i = 0; i < 4; i++) s[nt][i] = 0.f;
#pragma unroll
        for (int k8 = 0; k8 < 8; k8++) {
#pragma unroll
            for (int nt = 0; nt < 8; nt++) {
                uint32_t b0 = Ku[(nt * 8 + g) * FSTR + k8 * 8 + t];
                uint32_t b1 = Ku[(nt * 8 + g) * FSTR + k8 * 8 + t + 4];
                mma_tf32(s[nt], qf[k8][0], qf[k8][1], qf[k8][2], qf[k8][3], b0, b1);
            }
        }

        // ---- online softmax in registers ----
        float tm0 = -INFINITY, tm1 = -INFINITY;
#pragma unroll
        for (int nt = 0; nt < 8; nt++) {
            float b0 = bias[nt * 8 + 2 * t];
            float b1 = bias[nt * 8 + 2 * t + 1];
            s[nt][0] += b0; s[nt][1] += b1;
            s[nt][2] += b0; s[nt][3] += b1;
            tm0 = fmaxf(tm0, fmaxf(s[nt][0], s[nt][1]));
            tm1 = fmaxf(tm1, fmaxf(s[nt][2], s[nt][3]));
        }
        tm0 = fmaxf(tm0, __shfl_xor_sync(0xffffffffu, tm0, 1));
        tm0 = fmaxf(tm0, __shfl_xor_sync(0xffffffffu, tm0, 2));
        tm1 = fmaxf(tm1, __shfl_xor_sync(0xffffffffu, tm1, 1));
        tm1 = fmaxf(tm1, __shfl_xor_sync(0xffffffffu, tm1, 2));

        float mn0 = fmaxf(mr0, tm0), mn1 = fmaxf(mr1, tm1);
        float a0 = __expf(mr0 - mn0), a1 = __expf(mr1 - mn1);
        float ls0 = 0.f, ls1 = 0.f;
#pragma unroll
        for (int nt = 0; nt < 8; nt++) {
            float p0 = __expf(s[nt][0] - mn0);
            float p1 = __expf(s[nt][1] - mn0);
            float p2 = __expf(s[nt][2] - mn1);
            float p3 = __expf(s[nt][3] - mn1);
            ls0 += p0 + p1; ls1 += p2 + p3;
            uint2 u01 = { f2tf32(p0), f2tf32(p1) };
            uint2 u23 = { f2tf32(p2), f2tf32(p3) };
            *(uint2*)(Pw + g * FSTR + nt * 8 + 2 * t) = u01;
            *(uint2*)(Pw + (g + 8) * FSTR + nt * 8 + 2 * t) = u23;
        }
        ls0 += __shfl_xor_sync(0xffffffffu, ls0, 1);
        ls0 += __shfl_xor_sync(0xffffffffu, ls0, 2);
        ls1 += __shfl_xor_sync(0xffffffffu, ls1, 1);
        ls1 += __shfl_xor_sync(0xffffffffu, ls1, 2);

        mr0 = mn0; mr1 = mn1;
        l0 = l0 * a0 + ls0;
        l1 = l1 * a1 + ls1;
#pragma unroll
        for (int nt = 0; nt < 8; nt++) {
            of[nt][0] *= a0; of[nt][1] *= a0;
            of[nt][2] *= a1; of[nt][3] *= a1;
        }
        __syncwarp();

        // ---- O += P V ----
#pragma unroll
        for (int k8 = 0; k8 < 8; k8++) {
            uint32_t pa0 = Pw[g * FSTR + k8 * 8 + t];
            uint32_t pa1 = Pw[(g + 8) * FSTR + k8 * 8 + t];
            uint32_t pa2 = Pw[g * FSTR + k8 * 8 + t + 4];
            uint32_t pa3 = Pw[(g + 8) * FSTR + k8 * 8 + t + 4];
#pragma unroll
            for (int nt = 0; nt < 8; nt++) {
                uint32_t b0 = Vu[(nt * 8 + g) * VSTR + k8 * 8 + t];
                uint32_t b1 = Vu[(nt * 8 + g) * VSTR + k8 * 8 + t + 4];
                mma_tf32(of[nt], pa0, pa1, pa2, pa3, b0, b1);
            }
        }
        __syncthreads();
    }

    // ---- epilogue ----
    const float li0 = 1.f / l0, li1 = 1.f / l1;
    float* Og = g_A + (size_t)(b * SEQ + q0 + m0) * D_MODEL + h * DK;
#pragma unroll
    for (int nt = 0; nt < 8; nt++) {
        const int col = nt * 8 + 2 * t;
        *(float2*)(Og + (size_t)g * D_MODEL + col) =
            make_float2(of[nt][0] * li0, of[nt][1] * li0);
        *(float2*)(Og + (size_t)(g + 8) * D_MODEL + col) =
            make_float2(of[nt][2] * li1, of[nt][3] * li1);
    }
}

// =================================================================
// launch
// =================================================================
extern "C" void kernel_launch(void* const* d_in, const int* in_sizes, int n_in,
                              void* d_out, int out_size)
{
    const float* x    = (const float*)d_in[0];
    const int*   mask = (const int*)d_in[1];
    const float* Wq   = (const float*)d_in[2];
    const float* Wk   = (const float*)d_in[3];
    const float* Wv   = (const float*)d_in[4];
    const float* Wo   = (const float*)d_in[5];
    float* out = (float*)d_out;

    float *gq, *gk, *gv, *ga;
    cudaGetSymbolAddress((void**)&gq, g_Q);
    cudaGetSymbolAddress((void**)&gk, g_K);
    cudaGetSymbolAddress((void**)&gv, g_V);
    cudaGetSymbolAddress((void**)&ga, g_A);

    cudaFuncSetAttribute(gemm_qkv,
                         cudaFuncAttributeMaxDynamicSharedMemorySize, SMEM_GEMM);
    cudaFuncSetAttribute(gemm_mma,
                         cudaFuncAttributeMaxDynamicSharedMemorySize, SMEM_GEMM);
    cudaFuncSetAttribute(flash_mma,
                         cudaFuncAttributeMaxDynamicSharedMemorySize, SMEM_ATTN);

    dim3 qkv_grid(D_MODEL / TN, M_TOTAL / TM, 3);  // (4, 32, 3) = 384 CTAs
    gemm_qkv<<<qkv_grid, 256, SMEM_GEMM>>>(x, Wq, Wk, Wv, gq, gk, gv);

    dim3 attn_grid(SEQ / BQ, BATCH * NUM_HEADS);   // (16, 32) = 512 CTAs
    flash_mma<<<attn_grid, 256, SMEM_ATTN>>>(mask);

    dim3 ggrid(D_MODEL / TN, M_TOTAL / TM);        // (4, 32)
    gemm_mma<<<ggrid, 256, SMEM_GEMM>>>(ga, Wo, out);
}